// round 12
// baseline (speedup 1.0000x reference)
#include <cuda_runtime.h>
#include <cuda_fp16.h>
#include <cstdint>

typedef unsigned long long ull;

#define BB 64
#define FF 4
#define MM 4096
#define DD 1024
#define NITER 15
#define WD 16            // DD/64 sign-bit words (u64)
#define WDP 17           // padded sBits row stride (bank-conflict-free)
#define GRID_RUN 128

// ---------------- device scratch ----------------
__device__ ull g_est[2][BB * FF * WD];               // ping-pong estimate bits (1 = negative)
__device__ ull g_in[BB * WD];                        // input bits
__device__ ull g_cbD[FF * MM * WD];                  // codebook bits (cleanup)
__device__ __align__(16) int8_t g_cbT[(size_t)FF * DD * MM];   // codebook transposed s8 [f][d][m]
__device__ __align__(16) __half g_G[(size_t)FF * DD * DD];     // Gram: G[f] = C[f]^T C[f]
__device__ ull g_sync[NITER];                        // low32 = arrivals, high32 = mismatch count

// ---------------- helpers ----------------
__device__ __forceinline__ uint32_t smem_u32(const void* p) {
    return (uint32_t)__cvta_generic_to_shared(p);
}
__device__ __forceinline__ void ldm_x4(uint32_t& r0, uint32_t& r1, uint32_t& r2, uint32_t& r3, uint32_t addr) {
    asm volatile("ldmatrix.sync.aligned.m8n8.x4.shared.b16 {%0,%1,%2,%3}, [%4];\n"
                 : "=r"(r0), "=r"(r1), "=r"(r2), "=r"(r3) : "r"(addr));
}
__device__ __forceinline__ void ldm_x4_t(uint32_t& r0, uint32_t& r1, uint32_t& r2, uint32_t& r3, uint32_t addr) {
    asm volatile("ldmatrix.sync.aligned.m8n8.x4.trans.shared.b16 {%0,%1,%2,%3}, [%4];\n"
                 : "=r"(r0), "=r"(r1), "=r"(r2), "=r"(r3) : "r"(addr));
}
__device__ __forceinline__ void mma16816(float* c, uint32_t a0, uint32_t a1, uint32_t a2, uint32_t a3,
                                         uint32_t b0, uint32_t b1) {
    asm volatile("mma.sync.aligned.m16n8k16.row.col.f32.f16.f16.f32 "
                 "{%0,%1,%2,%3}, {%4,%5,%6,%7}, {%8,%9}, {%0,%1,%2,%3};\n"
                 : "+f"(c[0]), "+f"(c[1]), "+f"(c[2]), "+f"(c[3])
                 : "r"(a0), "r"(a1), "r"(a2), "r"(a3), "r"(b0), "r"(b1));
}
__device__ __forceinline__ void mma16832s8(int* c, uint32_t a0, uint32_t a1, uint32_t a2, uint32_t a3,
                                           uint32_t b0, uint32_t b1) {
    asm volatile("mma.sync.aligned.m16n8k32.row.col.s32.s8.s8.s32 "
                 "{%0,%1,%2,%3}, {%4,%5,%6,%7}, {%8,%9}, {%0,%1,%2,%3};\n"
                 : "+r"(c[0]), "+r"(c[1]), "+r"(c[2]), "+r"(c[3])
                 : "r"(a0), "r"(a1), "r"(a2), "r"(a3), "r"(b0), "r"(b1));
}
// 2 sign bits -> packed half2 of +-1 (bit=1 -> -1)
__device__ __forceinline__ uint32_t bexp(uint32_t t) {
    return 0x3C003C00u | ((t & 1u) << 15) | ((t & 2u) << 30);
}
// spread 16 bits to every 4th bit of a u64
__device__ __forceinline__ ull spr4(uint32_t x) {
    ull v = x & 0xFFFFull;
    v = (v | v << 24) & 0x000000FF000000FFull;
    v = (v | v << 12) & 0x000F000F000F000Full;
    v = (v | v << 6)  & 0x0303030303030303ull;
    v = (v | v << 3)  & 0x1111111111111111ull;
    return v;
}

// ---------------- pack kernels ----------------
// bits only: warp per codebook row
__global__ void k_pack_cb(const float* __restrict__ cb) {
    int row  = blockIdx.x * 4 + (threadIdx.x >> 5);
    int lane = threadIdx.x & 31;
    const float* src = cb + (size_t)row * DD;
    ull* dstb = g_cbD + row * WD;
    #pragma unroll
    for (int i = 0; i < 8; i++) {
        float4 v = *(const float4*)(src + i * 128 + lane * 4);
        unsigned b0 = __ballot_sync(0xffffffffu, v.x < 0.f);
        unsigned b1 = __ballot_sync(0xffffffffu, v.y < 0.f);
        unsigned b2 = __ballot_sync(0xffffffffu, v.z < 0.f);
        unsigned b3 = __ballot_sync(0xffffffffu, v.w < 0.f);
        if (lane == 0) {
            dstb[i * 2]     = spr4(b0) | (spr4(b1) << 1) | (spr4(b2) << 2) | (spr4(b3) << 3);
            dstb[i * 2 + 1] = spr4(b0 >> 16) | (spr4(b1 >> 16) << 1) | (spr4(b2 >> 16) << 2) | (spr4(b3 >> 16) << 3);
        }
    }
}

// transposed s8 copy CT[f][d][m] via smem 64x64 tiles
__global__ void k_pack_ct(const float* __restrict__ cb) {
    __shared__ int8_t tile[64][68];
    int bidx = blockIdx.x;
    int f = bidx >> 10, r2 = bidx & 1023, mt = r2 >> 4, dt = r2 & 15;
    int m0 = mt << 6, d0 = dt << 6;
    int t = threadIdx.x;
    const float* src = cb + (size_t)f * MM * DD + (size_t)m0 * DD + d0;
    #pragma unroll
    for (int p = 0; p < 4; p++) {
        int row = p * 16 + (t >> 4);
        int col = (t & 15) * 4;
        float4 v = *(const float4*)(src + (size_t)row * DD + col);
        tile[row][col]     = v.x < 0.f ? -1 : 1;
        tile[row][col + 1] = v.y < 0.f ? -1 : 1;
        tile[row][col + 2] = v.z < 0.f ? -1 : 1;
        tile[row][col + 3] = v.w < 0.f ? -1 : 1;
    }
    __syncthreads();
    int r = t >> 2, q = t & 3;
    uint32_t u[4];
    #pragma unroll
    for (int wq = 0; wq < 4; wq++) {
        uint32_t x = 0;
        #pragma unroll
        for (int jj = 0; jj < 4; jj++)
            x |= (uint32_t)(uint8_t)tile[q * 16 + wq * 4 + jj][r] << (jj * 8);
        u[wq] = x;
    }
    *(uint4*)(g_cbT + (size_t)f * DD * MM + (size_t)(d0 + r) * MM + m0 + q * 16) = *(uint4*)u;
}

__global__ void k_pack_est(const float* __restrict__ inp, const float* __restrict__ est0) {
    int row  = blockIdx.x * 4 + (threadIdx.x >> 5);
    int lane = threadIdx.x & 31;
    if (blockIdx.x == 0 && threadIdx.x < NITER) g_sync[threadIdx.x] = 0ull;
    const float* src;
    ull* dst;
    if (row < BB * FF) { src = est0 + (size_t)row * DD; dst = g_est[0] + row * WD; }
    else               { int b = row - BB * FF; src = inp + (size_t)b * DD; dst = g_in + b * WD; }
    ull lo = 0;
    #pragma unroll
    for (int i = 0; i < 32; i++) {
        unsigned bal = __ballot_sync(0xffffffffu, src[i * 32 + lane] < 0.f);
        if ((i & 1) == 0) lo = bal;
        else if (lane == 0) dst[i >> 1] = lo | ((ull)bal << 32);
    }
}

// ---------------- Gram (s8 MMA): G[f][d][d'] = sum_m CT[d][m]*CT[d'][m] ----------------
// grid 4*36 upper-triangle 128x128 tiles; 256 thr (8 warps: wm=w>>1 32i, wn=w&1 64j).
// K = 4096 m, chunks of 128 (double-buffered cp.async). smem 64 KB dynamic.
__device__ __forceinline__ void gram_load(int8_t* dI, int8_t* dJ,
                                          const int8_t* CfI, const int8_t* CfJ,
                                          int k0, int t) {
    #pragma unroll
    for (int q = 0; q < 4; q++) {
        int id = q * 256 + t;
        int r = id >> 3, c8 = id & 7;
        uint32_t a1 = smem_u32(dI + r * 128 + ((c8 ^ (r & 7)) << 4));
        asm volatile("cp.async.cg.shared.global [%0], [%1], 16;"
                     :: "r"(a1), "l"(CfI + (size_t)r * MM + k0 + c8 * 16));
        uint32_t a2 = smem_u32(dJ + r * 128 + ((c8 ^ (r & 7)) << 4));
        asm volatile("cp.async.cg.shared.global [%0], [%1], 16;"
                     :: "r"(a2), "l"(CfJ + (size_t)r * MM + k0 + c8 * 16));
    }
}

__global__ void __launch_bounds__(256) k_gram() {
    extern __shared__ __align__(16) char gsm[];
    int8_t* sI = (int8_t*)gsm;             // [2][128*128]
    int8_t* sJ = (int8_t*)(gsm + 32768);   // [2][128*128]

    int f = blockIdx.x / 36, pair = blockIdx.x % 36;
    int i = 0, rem = pair;
    while (rem >= 8 - i) { rem -= 8 - i; i++; }
    int j = i + rem;
    int gi = i << 7, gj = j << 7;
    int t = threadIdx.x, lane = t & 31, w = t >> 5;
    int wm = w >> 1, wn = w & 1;

    const int8_t* CfI = g_cbT + (size_t)f * DD * MM + (size_t)gi * MM;
    const int8_t* CfJ = g_cbT + (size_t)f * DD * MM + (size_t)gj * MM;

    int acc[2][8][4];
    #pragma unroll
    for (int a = 0; a < 2; a++)
        #pragma unroll
        for (int b2 = 0; b2 < 8; b2++)
            #pragma unroll
            for (int q = 0; q < 4; q++) acc[a][b2][q] = 0;

    gram_load(sI, sJ, CfI, CfJ, 0, t);
    asm volatile("cp.async.commit_group;");

    int l15 = lane & 15, lh = lane >> 4;
    int rb7 = (lane & 7) + ((lane >> 4) << 3);   // B row within 16
    int cb1 = (lane >> 3) & 1;                   // B c8 parity

    for (int c = 0; c < 32; c++) {
        __syncthreads();   // target buffer of next prefetch is free
        if (c + 1 < 32) {
            gram_load(sI + ((c + 1) & 1) * 16384, sJ + ((c + 1) & 1) * 16384,
                      CfI, CfJ, (c + 1) * 128, t);
            asm volatile("cp.async.commit_group;");
            asm volatile("cp.async.wait_group 1;");
        } else {
            asm volatile("cp.async.wait_group 0;");
        }
        __syncthreads();
        const int8_t* bI = sI + (c & 1) * 16384;
        const int8_t* bJ = sJ + (c & 1) * 16384;
        #pragma unroll
        for (int k32 = 0; k32 < 4; k32++) {
            uint32_t A[2][4];
            #pragma unroll
            for (int mi = 0; mi < 2; mi++) {
                int ra = wm * 32 + mi * 16 + l15;
                int c8 = k32 * 2 + lh;
                ldm_x4(A[mi][0], A[mi][1], A[mi][2], A[mi][3],
                       smem_u32(bI + ra * 128 + ((c8 ^ (ra & 7)) << 4)));
            }
            #pragma unroll
            for (int ng = 0; ng < 4; ng++) {
                int rB = wn * 64 + ng * 16 + rb7;
                int c8 = k32 * 2 + cb1;
                uint32_t B4[4];
                ldm_x4(B4[0], B4[1], B4[2], B4[3],
                       smem_u32(bJ + rB * 128 + ((c8 ^ (rB & 7)) << 4)));
                #pragma unroll
                for (int mi = 0; mi < 2; mi++) {
                    mma16832s8(acc[mi][ng * 2],     A[mi][0], A[mi][1], A[mi][2], A[mi][3], B4[0], B4[1]);
                    mma16832s8(acc[mi][ng * 2 + 1], A[mi][0], A[mi][1], A[mi][2], A[mi][3], B4[2], B4[3]);
                }
            }
        }
    }

    __half* Gf = g_G + (size_t)f * DD * DD;
    #pragma unroll
    for (int mi = 0; mi < 2; mi++)
        #pragma unroll
        for (int nf = 0; nf < 8; nf++) {
            int row = gi + wm * 32 + mi * 16 + (lane >> 2);
            int col = gj + wn * 64 + nf * 8 + (lane & 3) * 2;
            int* cc = acc[mi][nf];
            __half h0 = __int2half_rn(cc[0]), h1 = __int2half_rn(cc[1]);
            __half h2 = __int2half_rn(cc[2]), h3 = __int2half_rn(cc[3]);
            *(__half2*)&Gf[(size_t)row * DD + col]       = __halves2half2(h0, h1);
            *(__half2*)&Gf[(size_t)(row + 8) * DD + col] = __halves2half2(h2, h3);
            if (i != j) {
                Gf[(size_t)col * DD + row]           = h0;
                Gf[(size_t)(col + 1) * DD + row]     = h1;
                Gf[(size_t)col * DD + row + 8]       = h2;
                Gf[(size_t)(col + 1) * DD + row + 8] = h3;
            }
        }
}

// ---------------- persistent kernel: 15 iterations + cleanup ----------------
// grid = 128 CTAs: f = bid>>5, nt = bid&31. 512 threads = 16 warps (wm=w&3 16m, kq=w>>2 256k).
// Round-5 proven mainloop; padded bits; distributed epilogue; packed-u64 barrier; early exit.
#define SM_BITS 131072
#define SM_CP   139776
#define SM_MM   173568
#define SM_TOT  173600

__global__ void __launch_bounds__(512) k_run(float* __restrict__ out, int out_size) {
    extern __shared__ __align__(16) char smem[];
    __half* sG    = (__half*)smem;                 // resident G slice (all iterations)
    ull*    sBits = (ull*)(smem + SM_BITS);        // [64][17]
    float*  sCp   = (float*)(smem + SM_CP);        // [4][64][33]
    int*    sMm   = (int*)(smem + SM_MM);          // [0]=mismatch cnt, [1]=global mm
    char*   aux   = smem;                          // cleanup scratch (sG dead then)

    int t = threadIdx.x, lane = t & 31, w = t >> 5;
    int wm = w & 3, kq = w >> 2;
    int f = blockIdx.x >> 5, nt = blockIdx.x & 31, n0 = nt << 5;

    // load resident G slice: 1024 rows x 32 cols into groups c8=0..3 of 128B swizzled rows
    {
        const __half* Gf = g_G + (size_t)f * DD * DD + n0;
        for (int idx = t; idx < 4096; idx += 512) {
            int r = idx >> 2, c8 = idx & 3;
            uint4 v = *(const uint4*)(Gf + (size_t)r * DD + c8 * 8);
            *(uint4*)(sG + r * 64 + ((c8 ^ (r & 7)) << 3)) = v;
        }
    }

    int lq = lane & 3, lh = lane >> 4, l15 = lane & 15;
    int r0 = wm * 16 + (lane >> 2), r1 = r0 + 8;
    int shb = lq * 2;
    int b8 = t >> 3, rg = t & 7;    // epilogue mapping

    for (int it = 0; it < NITER; it++) {
        int p = it & 1;
        const ull* E = g_est[p];
        if (t == 0) sMm[0] = 0;

        // new_est bits: in ^ (xor of all est) ^ est_f  (padded rows)
        for (int idx = t; idx < BB * WD; idx += 512) {
            int b = idx >> 4, wd = idx & 15;
            ull x = g_in[idx];
            x ^= E[(b * FF + 0) * WD + wd] ^ E[(b * FF + 1) * WD + wd]
               ^ E[(b * FF + 2) * WD + wd] ^ E[(b * FF + 3) * WD + wd];
            sBits[b * WDP + wd] = x ^ E[(b * FF + f) * WD + wd];
        }
        __syncthreads();   // bits + (it=0) G-load visible

        float acc[4][4];
        #pragma unroll
        for (int a = 0; a < 4; a++)
            #pragma unroll
            for (int q = 0; q < 4; q++) acc[a][q] = 0.f;

        // round-5 mainloop: A from bits (regs), B via ldmatrix from resident sG
        #pragma unroll
        for (int c4 = 0; c4 < 4; c4++) {
            int C = kq * 4 + c4;
            ull w0 = sBits[r0 * WDP + C];
            ull w1 = sBits[r1 * WDP + C];
            #pragma unroll
            for (int k16 = 0; k16 < 4; k16++) {
                int sh = k16 * 16 + shb;
                uint32_t t0 = (uint32_t)(w0 >> sh), t1 = (uint32_t)(w1 >> sh);
                uint32_t a0 = bexp(t0), a1 = bexp(t1);
                uint32_t a2 = bexp(t0 >> 8), a3 = bexp(t1 >> 8);
                int br = C * 64 + k16 * 16 + l15;
                uint32_t b0, b1, b2, b3;
                int bc8 = lh;
                ldm_x4_t(b0, b1, b2, b3, smem_u32(sG + br * 64 + ((bc8 ^ (br & 7)) << 3)));
                mma16816(acc[0], a0, a1, a2, a3, b0, b1);
                mma16816(acc[1], a0, a1, a2, a3, b2, b3);
                bc8 = 2 + lh;
                ldm_x4_t(b0, b1, b2, b3, smem_u32(sG + br * 64 + ((bc8 ^ (br & 7)) << 3)));
                mma16816(acc[2], a0, a1, a2, a3, b0, b1);
                mma16816(acc[3], a0, a1, a2, a3, b2, b3);
            }
        }

        // stage K-partials: sCp[kq][64][33]
        {
            float* P = sCp + kq * 2112;
            #pragma unroll
            for (int j = 0; j < 4; j++) {
                P[r0 * 33 + j * 8 + shb]     = acc[j][0];
                P[r0 * 33 + j * 8 + shb + 1] = acc[j][1];
                P[r1 * 33 + j * 8 + shb]     = acc[j][2];
                P[r1 * 33 + j * 8 + shb + 1] = acc[j][3];
            }
        }
        __syncthreads();

        // distributed reduce + pack: thread = (batch b8, col-group rg of 4)
        {
            uint32_t word = 0;
            #pragma unroll
            for (int i2 = 0; i2 < 4; i2++) {
                int col = rg * 4 + i2;
                float s = sCp[b8 * 33 + col] + sCp[2112 + b8 * 33 + col]
                        + sCp[4224 + b8 * 33 + col] + sCp[6336 + b8 * 33 + col];
                word |= (uint32_t)(s < 0.f) << col;    // sign(0)=+1 -> strict <0
            }
            word |= __shfl_down_sync(0xffffffffu, word, 4, 8);
            word |= __shfl_down_sync(0xffffffffu, word, 2, 8);
            word |= __shfl_down_sync(0xffffffffu, word, 1, 8);
            bool chg = false;
            if (rg == 0) {
                int ei = (b8 * FF + f) * 32 + nt;
                uint32_t old = ((const uint32_t*)g_est[p])[ei];
                ((uint32_t*)g_est[p ^ 1])[ei] = word;
                chg = (word != old);
            }
            unsigned msk = __ballot_sync(0xffffffffu, chg);
            if (lane == 0 && msk) atomicAdd(&sMm[0], __popc(msk));
        }
        __syncthreads();

        // packed barrier: one release-atomic per CTA (arrive + mismatch), thread0 polls
        if (t == 0) {
            asm volatile("membar.gl;" ::: "memory");
            ull val = 1ull | ((ull)(unsigned)sMm[0] << 32);
            asm volatile("red.release.gpu.global.add.u64 [%0], %1;"
                         :: "l"(g_sync + it), "l"(val) : "memory");
            ull v;
            do {
                asm volatile("ld.acquire.gpu.global.b64 %0, [%1];"
                             : "=l"(v) : "l"(g_sync + it) : "memory");
            } while ((unsigned)v < GRID_RUN);
            sMm[1] = (int)(v >> 32);
        }
        __syncthreads();
        if (sMm[1] == 0) break;   // fixed point: all later iterations identical
    }
    __syncthreads();

    // ---------------- cleanup: argmax|sim| per (b, f), est floats, iters/conv ----------------
    {
        int f2 = blockIdx.x >> 5, bg = blockIdx.x & 31;   // 2 batches per CTA
        ull* sE = (ull*)aux;                              // 2 x 16 ull
        int* rA = (int*)(aux + 256);
        int* rI = (int*)(aux + 256 + 2048);
        const ull* Ef = g_est[NITER & 1];

        if (t < 32) {
            int j = t >> 4, wd = t & 15;
            sE[j * WD + wd] = Ef[(size_t)((bg * 2 + j) * FF + f2) * WD + wd];
        }
        __syncthreads();

        const ull* cb = g_cbD + (size_t)f2 * MM * WD;
        int bestA[2] = {-1, -1}, bestI[2] = {0, 0};
        for (int m = t; m < MM; m += 512) {
            ull rb[WD];
            const ull* rp = cb + (size_t)m * WD;
            #pragma unroll
            for (int q = 0; q < WD; q++) rb[q] = rp[q];
            #pragma unroll
            for (int j = 0; j < 2; j++) {
                int h = 0;
                #pragma unroll
                for (int q = 0; q < WD; q++) h += __popcll(rb[q] ^ sE[j * WD + q]);
                int s = DD - 2 * h;
                int a = s < 0 ? -s : s;
                if (a > bestA[j]) { bestA[j] = a; bestI[j] = m; }
            }
        }

        #pragma unroll
        for (int j = 0; j < 2; j++) {
            __syncthreads();
            rA[t] = bestA[j]; rI[t] = bestI[j];
            __syncthreads();
            for (int off = 256; off; off >>= 1) {
                if (t < off) {
                    int a2 = rA[t + off], i2 = rI[t + off];
                    if (a2 > rA[t] || (a2 == rA[t] && i2 < rI[t])) { rA[t] = a2; rI[t] = i2; }
                }
                __syncthreads();
            }
            int idx = (bg * 2 + j) * FF + f2;
            if (t == 0 && idx < out_size) out[idx] = (float)rI[0];
            if (out_size >= 256 + BB * FF * DD) {
                float* oe = out + 256 + (size_t)idx * DD;
                for (int d = t; d < DD; d += 512) {
                    int bit = (int)((sE[j * WD + (d >> 6)] >> (d & 63)) & 1ULL);
                    oe[d] = bit ? -1.f : 1.f;
                }
            }
        }

        if (blockIdx.x == 0 && t == 0 && out_size >= 256 + BB * FF * DD + 2) {
            int iters = NITER, conv = 0;
            for (int tt = 0; tt < NITER; tt++)
                if ((int)(g_sync[tt] >> 32) == 0) { iters = tt + 1; conv = 1; break; }
            out[256 + BB * FF * DD]     = (float)iters;
            out[256 + BB * FF * DD + 1] = (float)conv;
        }
    }
}

// ---------------- launch ----------------
extern "C" void kernel_launch(void* const* d_in, const int* in_sizes, int n_in,
                              void* d_out, int out_size) {
    const float* input = nullptr;
    const float* est0  = nullptr;
    const float* cb    = nullptr;
    for (int i = 0; i < n_in; i++) {
        if (in_sizes[i] == BB * DD)            input = (const float*)d_in[i];
        else if (in_sizes[i] == BB * FF * DD)  est0  = (const float*)d_in[i];
        else if (in_sizes[i] == FF * MM * DD)  cb    = (const float*)d_in[i];
    }
    cudaFuncSetAttribute(k_run,  cudaFuncAttributeMaxDynamicSharedMemorySize, SM_TOT);
    cudaFuncSetAttribute(k_gram, cudaFuncAttributeMaxDynamicSharedMemorySize, 65536);
    k_pack_est<<<80, 128>>>(input, est0);
    k_pack_cb<<<FF * MM / 4, 128>>>(cb);
    k_pack_ct<<<FF * 1024, 256>>>(cb);
    k_gram<<<FF * 36, 256, 65536>>>();
    k_run<<<GRID_RUN, 512, SM_TOT>>>((float*)d_out, out_size);
}

// round 13
// speedup vs baseline: 1.0004x; 1.0004x over previous
#include <cuda_runtime.h>
#include <cuda_fp16.h>
#include <cstdint>

typedef unsigned long long ull;

#define BB 64
#define FF 4
#define MM 4096
#define DD 1024
#define NITER 15
#define WD 16            // DD/64 sign-bit words (u64)
#define WDP 17           // padded sBits row stride (bank-conflict-free)
#define GRID_RUN 128

// ---------------- device scratch ----------------
__device__ ull g_est[2][BB * FF * WD];               // ping-pong estimate bits (1 = negative)
__device__ ull g_in[BB * WD];                        // input bits
__device__ ull g_cbD[FF * MM * WD];                  // codebook bits (cleanup)
__device__ __align__(16) int8_t g_cbT[(size_t)FF * DD * MM];   // codebook transposed s8 [f][d][m]
__device__ __align__(16) __half g_G[(size_t)FF * DD * DD];     // Gram: G[f] = C[f]^T C[f]
__device__ ull g_sync[NITER];                        // low32 = arrivals, high32 = mismatch count

// ---------------- helpers ----------------
__device__ __forceinline__ uint32_t smem_u32(const void* p) {
    return (uint32_t)__cvta_generic_to_shared(p);
}
__device__ __forceinline__ void ldm_x4(uint32_t& r0, uint32_t& r1, uint32_t& r2, uint32_t& r3, uint32_t addr) {
    asm volatile("ldmatrix.sync.aligned.m8n8.x4.shared.b16 {%0,%1,%2,%3}, [%4];\n"
                 : "=r"(r0), "=r"(r1), "=r"(r2), "=r"(r3) : "r"(addr));
}
__device__ __forceinline__ void ldm_x4_t(uint32_t& r0, uint32_t& r1, uint32_t& r2, uint32_t& r3, uint32_t addr) {
    asm volatile("ldmatrix.sync.aligned.m8n8.x4.trans.shared.b16 {%0,%1,%2,%3}, [%4];\n"
                 : "=r"(r0), "=r"(r1), "=r"(r2), "=r"(r3) : "r"(addr));
}
__device__ __forceinline__ void mma16816(float* c, uint32_t a0, uint32_t a1, uint32_t a2, uint32_t a3,
                                         uint32_t b0, uint32_t b1) {
    asm volatile("mma.sync.aligned.m16n8k16.row.col.f32.f16.f16.f32 "
                 "{%0,%1,%2,%3}, {%4,%5,%6,%7}, {%8,%9}, {%0,%1,%2,%3};\n"
                 : "+f"(c[0]), "+f"(c[1]), "+f"(c[2]), "+f"(c[3])
                 : "r"(a0), "r"(a1), "r"(a2), "r"(a3), "r"(b0), "r"(b1));
}
__device__ __forceinline__ void mma16832s8(int* c, uint32_t a0, uint32_t a1, uint32_t a2, uint32_t a3,
                                           uint32_t b0, uint32_t b1) {
    asm volatile("mma.sync.aligned.m16n8k32.row.col.s32.s8.s8.s32 "
                 "{%0,%1,%2,%3}, {%4,%5,%6,%7}, {%8,%9}, {%0,%1,%2,%3};\n"
                 : "+r"(c[0]), "+r"(c[1]), "+r"(c[2]), "+r"(c[3])
                 : "r"(a0), "r"(a1), "r"(a2), "r"(a3), "r"(b0), "r"(b1));
}
// 2 sign bits -> packed half2 of +-1 (bit=1 -> -1)
__device__ __forceinline__ uint32_t bexp(uint32_t t) {
    return 0x3C003C00u | ((t & 1u) << 15) | ((t & 2u) << 30);
}
// spread 16 bits to every 4th bit of a u64
__device__ __forceinline__ ull spr4(uint32_t x) {
    ull v = x & 0xFFFFull;
    v = (v | v << 24) & 0x000000FF000000FFull;
    v = (v | v << 12) & 0x000F000F000F000Full;
    v = (v | v << 6)  & 0x0303030303030303ull;
    v = (v | v << 3)  & 0x1111111111111111ull;
    return v;
}

// ---------------- pack kernels ----------------
// bits only: warp per codebook row
__global__ void k_pack_cb(const float* __restrict__ cb) {
    int row  = blockIdx.x * 4 + (threadIdx.x >> 5);
    int lane = threadIdx.x & 31;
    const float* src = cb + (size_t)row * DD;
    ull* dstb = g_cbD + row * WD;
    #pragma unroll
    for (int i = 0; i < 8; i++) {
        float4 v = *(const float4*)(src + i * 128 + lane * 4);
        unsigned b0 = __ballot_sync(0xffffffffu, v.x < 0.f);
        unsigned b1 = __ballot_sync(0xffffffffu, v.y < 0.f);
        unsigned b2 = __ballot_sync(0xffffffffu, v.z < 0.f);
        unsigned b3 = __ballot_sync(0xffffffffu, v.w < 0.f);
        if (lane == 0) {
            dstb[i * 2]     = spr4(b0) | (spr4(b1) << 1) | (spr4(b2) << 2) | (spr4(b3) << 3);
            dstb[i * 2 + 1] = spr4(b0 >> 16) | (spr4(b1 >> 16) << 1) | (spr4(b2 >> 16) << 2) | (spr4(b3 >> 16) << 3);
        }
    }
}

// transposed s8 copy CT[f][d][m] via smem 64x64 tiles
__global__ void k_pack_ct(const float* __restrict__ cb) {
    __shared__ int8_t tile[64][68];
    int bidx = blockIdx.x;
    int f = bidx >> 10, r2 = bidx & 1023, mt = r2 >> 4, dt = r2 & 15;
    int m0 = mt << 6, d0 = dt << 6;
    int t = threadIdx.x;
    const float* src = cb + (size_t)f * MM * DD + (size_t)m0 * DD + d0;
    #pragma unroll
    for (int p = 0; p < 4; p++) {
        int row = p * 16 + (t >> 4);
        int col = (t & 15) * 4;
        float4 v = *(const float4*)(src + (size_t)row * DD + col);
        tile[row][col]     = v.x < 0.f ? -1 : 1;
        tile[row][col + 1] = v.y < 0.f ? -1 : 1;
        tile[row][col + 2] = v.z < 0.f ? -1 : 1;
        tile[row][col + 3] = v.w < 0.f ? -1 : 1;
    }
    __syncthreads();
    int r = t >> 2, q = t & 3;
    uint32_t u[4];
    #pragma unroll
    for (int wq = 0; wq < 4; wq++) {
        uint32_t x = 0;
        #pragma unroll
        for (int jj = 0; jj < 4; jj++)
            x |= (uint32_t)(uint8_t)tile[q * 16 + wq * 4 + jj][r] << (jj * 8);
        u[wq] = x;
    }
    *(uint4*)(g_cbT + (size_t)f * DD * MM + (size_t)(d0 + r) * MM + m0 + q * 16) = *(uint4*)u;
}

__global__ void k_pack_est(const float* __restrict__ inp, const float* __restrict__ est0) {
    int row  = blockIdx.x * 4 + (threadIdx.x >> 5);
    int lane = threadIdx.x & 31;
    if (blockIdx.x == 0 && threadIdx.x < NITER) g_sync[threadIdx.x] = 0ull;
    const float* src;
    ull* dst;
    if (row < BB * FF) { src = est0 + (size_t)row * DD; dst = g_est[0] + row * WD; }
    else               { int b = row - BB * FF; src = inp + (size_t)b * DD; dst = g_in + b * WD; }
    ull lo = 0;
    #pragma unroll
    for (int i = 0; i < 32; i++) {
        unsigned bal = __ballot_sync(0xffffffffu, src[i * 32 + lane] < 0.f);
        if ((i & 1) == 0) lo = bal;
        else if (lane == 0) dst[i >> 1] = lo | ((ull)bal << 32);
    }
}

// ---------------- Gram (s8 MMA): G[f][d][d'] = sum_m CT[d][m]*CT[d'][m] ----------------
// grid 4*36 upper-triangle 128x128 tiles; 256 thr (8 warps: wm=w>>1 32i, wn=w&1 64j).
// K = 4096 m, chunks of 128 (double-buffered cp.async). smem 64 KB dynamic.
__device__ __forceinline__ void gram_load(int8_t* dI, int8_t* dJ,
                                          const int8_t* CfI, const int8_t* CfJ,
                                          int k0, int t) {
    #pragma unroll
    for (int q = 0; q < 4; q++) {
        int id = q * 256 + t;
        int r = id >> 3, c8 = id & 7;
        uint32_t a1 = smem_u32(dI + r * 128 + ((c8 ^ (r & 7)) << 4));
        asm volatile("cp.async.cg.shared.global [%0], [%1], 16;"
                     :: "r"(a1), "l"(CfI + (size_t)r * MM + k0 + c8 * 16));
        uint32_t a2 = smem_u32(dJ + r * 128 + ((c8 ^ (r & 7)) << 4));
        asm volatile("cp.async.cg.shared.global [%0], [%1], 16;"
                     :: "r"(a2), "l"(CfJ + (size_t)r * MM + k0 + c8 * 16));
    }
}

__global__ void __launch_bounds__(256) k_gram() {
    extern __shared__ __align__(16) char gsm[];
    int8_t* sI = (int8_t*)gsm;             // [2][128*128]
    int8_t* sJ = (int8_t*)(gsm + 32768);   // [2][128*128]

    int f = blockIdx.x / 36, pair = blockIdx.x % 36;
    int i = 0, rem = pair;
    while (rem >= 8 - i) { rem -= 8 - i; i++; }
    int j = i + rem;
    int gi = i << 7, gj = j << 7;
    int t = threadIdx.x, lane = t & 31, w = t >> 5;
    int wm = w >> 1, wn = w & 1;

    const int8_t* CfI = g_cbT + (size_t)f * DD * MM + (size_t)gi * MM;
    const int8_t* CfJ = g_cbT + (size_t)f * DD * MM + (size_t)gj * MM;

    int acc[2][8][4];
    #pragma unroll
    for (int a = 0; a < 2; a++)
        #pragma unroll
        for (int b2 = 0; b2 < 8; b2++)
            #pragma unroll
            for (int q = 0; q < 4; q++) acc[a][b2][q] = 0;

    gram_load(sI, sJ, CfI, CfJ, 0, t);
    asm volatile("cp.async.commit_group;");

    int l15 = lane & 15, lh = lane >> 4;
    int rb7 = (lane & 7) + ((lane >> 4) << 3);   // B row within 16
    int cb1 = (lane >> 3) & 1;                   // B c8 parity

    for (int c = 0; c < 32; c++) {
        __syncthreads();   // target buffer of next prefetch is free
        if (c + 1 < 32) {
            gram_load(sI + ((c + 1) & 1) * 16384, sJ + ((c + 1) & 1) * 16384,
                      CfI, CfJ, (c + 1) * 128, t);
            asm volatile("cp.async.commit_group;");
            asm volatile("cp.async.wait_group 1;");
        } else {
            asm volatile("cp.async.wait_group 0;");
        }
        __syncthreads();
        const int8_t* bI = sI + (c & 1) * 16384;
        const int8_t* bJ = sJ + (c & 1) * 16384;
        #pragma unroll
        for (int k32 = 0; k32 < 4; k32++) {
            uint32_t A[2][4];
            #pragma unroll
            for (int mi = 0; mi < 2; mi++) {
                int ra = wm * 32 + mi * 16 + l15;
                int c8 = k32 * 2 + lh;
                ldm_x4(A[mi][0], A[mi][1], A[mi][2], A[mi][3],
                       smem_u32(bI + ra * 128 + ((c8 ^ (ra & 7)) << 4)));
            }
            #pragma unroll
            for (int ng = 0; ng < 4; ng++) {
                int rB = wn * 64 + ng * 16 + rb7;
                int c8 = k32 * 2 + cb1;
                uint32_t B4[4];
                ldm_x4(B4[0], B4[1], B4[2], B4[3],
                       smem_u32(bJ + rB * 128 + ((c8 ^ (rB & 7)) << 4)));
                #pragma unroll
                for (int mi = 0; mi < 2; mi++) {
                    mma16832s8(acc[mi][ng * 2],     A[mi][0], A[mi][1], A[mi][2], A[mi][3], B4[0], B4[1]);
                    mma16832s8(acc[mi][ng * 2 + 1], A[mi][0], A[mi][1], A[mi][2], A[mi][3], B4[2], B4[3]);
                }
            }
        }
    }

    __half* Gf = g_G + (size_t)f * DD * DD;
    #pragma unroll
    for (int mi = 0; mi < 2; mi++)
        #pragma unroll
        for (int nf = 0; nf < 8; nf++) {
            int row = gi + wm * 32 + mi * 16 + (lane >> 2);
            int col = gj + wn * 64 + nf * 8 + (lane & 3) * 2;
            int* cc = acc[mi][nf];
            __half h0 = __int2half_rn(cc[0]), h1 = __int2half_rn(cc[1]);
            __half h2 = __int2half_rn(cc[2]), h3 = __int2half_rn(cc[3]);
            *(__half2*)&Gf[(size_t)row * DD + col]       = __halves2half2(h0, h1);
            *(__half2*)&Gf[(size_t)(row + 8) * DD + col] = __halves2half2(h2, h3);
            if (i != j) {
                Gf[(size_t)col * DD + row]           = h0;
                Gf[(size_t)(col + 1) * DD + row]     = h1;
                Gf[(size_t)col * DD + row + 8]       = h2;
                Gf[(size_t)(col + 1) * DD + row + 8] = h3;
            }
        }
}

// ---------------- persistent kernel: 15 iterations + cleanup ----------------
// grid = 128 CTAs: f = bid>>5, nt = bid&31. 512 threads = 16 warps (wm=w&3 16m, kq=w>>2 256k).
// Round-5 proven mainloop; padded bits; distributed epilogue; packed-u64 barrier; early exit.
#define SM_BITS 131072
#define SM_CP   139776
#define SM_MM   173568
#define SM_TOT  173600

__global__ void __launch_bounds__(512) k_run(float* __restrict__ out, int out_size) {
    extern __shared__ __align__(16) char smem[];
    __half* sG    = (__half*)smem;                 // resident G slice (all iterations)
    ull*    sBits = (ull*)(smem + SM_BITS);        // [64][17]
    float*  sCp   = (float*)(smem + SM_CP);        // [4][64][33]
    int*    sMm   = (int*)(smem + SM_MM);          // [0]=mismatch cnt, [1]=global mm
    char*   aux   = smem;                          // cleanup scratch (sG dead then)

    int t = threadIdx.x, lane = t & 31, w = t >> 5;
    int wm = w & 3, kq = w >> 2;
    int f = blockIdx.x >> 5, nt = blockIdx.x & 31, n0 = nt << 5;

    // load resident G slice: 1024 rows x 32 cols into groups c8=0..3 of 128B swizzled rows
    {
        const __half* Gf = g_G + (size_t)f * DD * DD + n0;
        for (int idx = t; idx < 4096; idx += 512) {
            int r = idx >> 2, c8 = idx & 3;
            uint4 v = *(const uint4*)(Gf + (size_t)r * DD + c8 * 8);
            *(uint4*)(sG + r * 64 + ((c8 ^ (r & 7)) << 3)) = v;
        }
    }

    int lq = lane & 3, lh = lane >> 4, l15 = lane & 15;
    int r0 = wm * 16 + (lane >> 2), r1 = r0 + 8;
    int shb = lq * 2;
    int b8 = t >> 3, rg = t & 7;    // epilogue mapping

    for (int it = 0; it < NITER; it++) {
        int p = it & 1;
        const ull* E = g_est[p];
        if (t == 0) sMm[0] = 0;

        // new_est bits: in ^ (xor of all est) ^ est_f  (padded rows)
        for (int idx = t; idx < BB * WD; idx += 512) {
            int b = idx >> 4, wd = idx & 15;
            ull x = g_in[idx];
            x ^= E[(b * FF + 0) * WD + wd] ^ E[(b * FF + 1) * WD + wd]
               ^ E[(b * FF + 2) * WD + wd] ^ E[(b * FF + 3) * WD + wd];
            sBits[b * WDP + wd] = x ^ E[(b * FF + f) * WD + wd];
        }
        __syncthreads();   // bits + (it=0) G-load visible

        float acc[4][4];
        #pragma unroll
        for (int a = 0; a < 4; a++)
            #pragma unroll
            for (int q = 0; q < 4; q++) acc[a][q] = 0.f;

        // round-5 mainloop: A from bits (regs), B via ldmatrix from resident sG
        #pragma unroll
        for (int c4 = 0; c4 < 4; c4++) {
            int C = kq * 4 + c4;
            ull w0 = sBits[r0 * WDP + C];
            ull w1 = sBits[r1 * WDP + C];
            #pragma unroll
            for (int k16 = 0; k16 < 4; k16++) {
                int sh = k16 * 16 + shb;
                uint32_t t0 = (uint32_t)(w0 >> sh), t1 = (uint32_t)(w1 >> sh);
                uint32_t a0 = bexp(t0), a1 = bexp(t1);
                uint32_t a2 = bexp(t0 >> 8), a3 = bexp(t1 >> 8);
                int br = C * 64 + k16 * 16 + l15;
                uint32_t b0, b1, b2, b3;
                int bc8 = lh;
                ldm_x4_t(b0, b1, b2, b3, smem_u32(sG + br * 64 + ((bc8 ^ (br & 7)) << 3)));
                mma16816(acc[0], a0, a1, a2, a3, b0, b1);
                mma16816(acc[1], a0, a1, a2, a3, b2, b3);
                bc8 = 2 + lh;
                ldm_x4_t(b0, b1, b2, b3, smem_u32(sG + br * 64 + ((bc8 ^ (br & 7)) << 3)));
                mma16816(acc[2], a0, a1, a2, a3, b0, b1);
                mma16816(acc[3], a0, a1, a2, a3, b2, b3);
            }
        }

        // stage K-partials: sCp[kq][64][33]
        {
            float* P = sCp + kq * 2112;
            #pragma unroll
            for (int j = 0; j < 4; j++) {
                P[r0 * 33 + j * 8 + shb]     = acc[j][0];
                P[r0 * 33 + j * 8 + shb + 1] = acc[j][1];
                P[r1 * 33 + j * 8 + shb]     = acc[j][2];
                P[r1 * 33 + j * 8 + shb + 1] = acc[j][3];
            }
        }
        __syncthreads();

        // distributed reduce + pack: thread = (batch b8, col-group rg of 4)
        {
            uint32_t word = 0;
            #pragma unroll
            for (int i2 = 0; i2 < 4; i2++) {
                int col = rg * 4 + i2;
                float s = sCp[b8 * 33 + col] + sCp[2112 + b8 * 33 + col]
                        + sCp[4224 + b8 * 33 + col] + sCp[6336 + b8 * 33 + col];
                word |= (uint32_t)(s < 0.f) << col;    // sign(0)=+1 -> strict <0
            }
            word |= __shfl_down_sync(0xffffffffu, word, 4, 8);
            word |= __shfl_down_sync(0xffffffffu, word, 2, 8);
            word |= __shfl_down_sync(0xffffffffu, word, 1, 8);
            bool chg = false;
            if (rg == 0) {
                int ei = (b8 * FF + f) * 32 + nt;
                uint32_t old = ((const uint32_t*)g_est[p])[ei];
                ((uint32_t*)g_est[p ^ 1])[ei] = word;
                chg = (word != old);
            }
            unsigned msk = __ballot_sync(0xffffffffu, chg);
            if (lane == 0 && msk) atomicAdd(&sMm[0], __popc(msk));
        }
        __syncthreads();

        // packed barrier: one release-atomic per CTA (arrive + mismatch), thread0 polls
        if (t == 0) {
            asm volatile("membar.gl;" ::: "memory");
            ull val = 1ull | ((ull)(unsigned)sMm[0] << 32);
            asm volatile("red.release.gpu.global.add.u64 [%0], %1;"
                         :: "l"(g_sync + it), "l"(val) : "memory");
            ull v;
            do {
                asm volatile("ld.acquire.gpu.global.b64 %0, [%1];"
                             : "=l"(v) : "l"(g_sync + it) : "memory");
            } while ((unsigned)v < GRID_RUN);
            sMm[1] = (int)(v >> 32);
        }
        __syncthreads();
        if (sMm[1] == 0) break;   // fixed point: all later iterations identical
    }
    __syncthreads();

    // ---------------- cleanup: argmax|sim| per (b, f), est floats, iters/conv ----------------
    {
        int f2 = blockIdx.x >> 5, bg = blockIdx.x & 31;   // 2 batches per CTA
        ull* sE = (ull*)aux;                              // 2 x 16 ull
        int* rA = (int*)(aux + 256);
        int* rI = (int*)(aux + 256 + 2048);
        const ull* Ef = g_est[NITER & 1];

        if (t < 32) {
            int j = t >> 4, wd = t & 15;
            sE[j * WD + wd] = Ef[(size_t)((bg * 2 + j) * FF + f2) * WD + wd];
        }
        __syncthreads();

        const ull* cb = g_cbD + (size_t)f2 * MM * WD;
        int bestA[2] = {-1, -1}, bestI[2] = {0, 0};
        for (int m = t; m < MM; m += 512) {
            ull rb[WD];
            const ull* rp = cb + (size_t)m * WD;
            #pragma unroll
            for (int q = 0; q < WD; q++) rb[q] = rp[q];
            #pragma unroll
            for (int j = 0; j < 2; j++) {
                int h = 0;
                #pragma unroll
                for (int q = 0; q < WD; q++) h += __popcll(rb[q] ^ sE[j * WD + q]);
                int s = DD - 2 * h;
                int a = s < 0 ? -s : s;
                if (a > bestA[j]) { bestA[j] = a; bestI[j] = m; }
            }
        }

        #pragma unroll
        for (int j = 0; j < 2; j++) {
            __syncthreads();
            rA[t] = bestA[j]; rI[t] = bestI[j];
            __syncthreads();
            for (int off = 256; off; off >>= 1) {
                if (t < off) {
                    int a2 = rA[t + off], i2 = rI[t + off];
                    if (a2 > rA[t] || (a2 == rA[t] && i2 < rI[t])) { rA[t] = a2; rI[t] = i2; }
                }
                __syncthreads();
            }
            int idx = (bg * 2 + j) * FF + f2;
            if (t == 0 && idx < out_size) out[idx] = (float)rI[0];
            if (out_size >= 256 + BB * FF * DD) {
                float* oe = out + 256 + (size_t)idx * DD;
                for (int d = t; d < DD; d += 512) {
                    int bit = (int)((sE[j * WD + (d >> 6)] >> (d & 63)) & 1ULL);
                    oe[d] = bit ? -1.f : 1.f;
                }
            }
        }

        if (blockIdx.x == 0 && t == 0 && out_size >= 256 + BB * FF * DD + 2) {
            int iters = NITER, conv = 0;
            for (int tt = 0; tt < NITER; tt++)
                if ((int)(g_sync[tt] >> 32) == 0) { iters = tt + 1; conv = 1; break; }
            out[256 + BB * FF * DD]     = (float)iters;
            out[256 + BB * FF * DD + 1] = (float)conv;
        }
    }
}

// ---------------- launch ----------------
extern "C" void kernel_launch(void* const* d_in, const int* in_sizes, int n_in,
                              void* d_out, int out_size) {
    const float* input = nullptr;
    const float* est0  = nullptr;
    const float* cb    = nullptr;
    for (int i = 0; i < n_in; i++) {
        if (in_sizes[i] == BB * DD)            input = (const float*)d_in[i];
        else if (in_sizes[i] == BB * FF * DD)  est0  = (const float*)d_in[i];
        else if (in_sizes[i] == FF * MM * DD)  cb    = (const float*)d_in[i];
    }
    cudaFuncSetAttribute(k_run,  cudaFuncAttributeMaxDynamicSharedMemorySize, SM_TOT);
    cudaFuncSetAttribute(k_gram, cudaFuncAttributeMaxDynamicSharedMemorySize, 65536);
    k_pack_est<<<80, 128>>>(input, est0);
    k_pack_cb<<<FF * MM / 4, 128>>>(cb);
    k_pack_ct<<<FF * 1024, 256>>>(cb);
    k_gram<<<FF * 36, 256, 65536>>>();
    k_run<<<GRID_RUN, 512, SM_TOT>>>((float*)d_out, out_size);
}

// round 15
// speedup vs baseline: 1.2741x; 1.2735x over previous
#include <cuda_runtime.h>
#include <cuda_fp16.h>
#include <cstdint>

typedef unsigned long long ull;

#define BB 64
#define FF 4
#define MM 4096
#define DD 1024
#define NITER 15
#define WD 16            // DD/64 sign-bit words (u64)
#define WDP 17           // padded sBits row stride (bank-conflict-free)
#define GRID_RUN 128

// ---------------- device scratch ----------------
__device__ ull g_est[2][BB * FF * WD];               // ping-pong estimate bits (1 = negative)
__device__ ull g_in[BB * WD];                        // input bits
__device__ ull g_cbD[FF * MM * WD];                  // codebook bits (cleanup)
__device__ __align__(16) __half g_cb16[(size_t)FF * MM * DD];  // codebook fp16
__device__ __align__(16) __half g_G[(size_t)FF * DD * DD];     // Gram: G[f] = C[f]^T C[f]
__device__ ull g_sync[NITER];                        // low32 = arrivals, high32 = mismatch count

// ---------------- helpers ----------------
__device__ __forceinline__ uint32_t smem_u32(const void* p) {
    return (uint32_t)__cvta_generic_to_shared(p);
}
__device__ __forceinline__ void ldm_x4_t(uint32_t& r0, uint32_t& r1, uint32_t& r2, uint32_t& r3, uint32_t addr) {
    asm volatile("ldmatrix.sync.aligned.m8n8.x4.trans.shared.b16 {%0,%1,%2,%3}, [%4];\n"
                 : "=r"(r0), "=r"(r1), "=r"(r2), "=r"(r3) : "r"(addr));
}
__device__ __forceinline__ void mma16816(float* c, uint32_t a0, uint32_t a1, uint32_t a2, uint32_t a3,
                                         uint32_t b0, uint32_t b1) {
    asm volatile("mma.sync.aligned.m16n8k16.row.col.f32.f16.f16.f32 "
                 "{%0,%1,%2,%3}, {%4,%5,%6,%7}, {%8,%9}, {%0,%1,%2,%3};\n"
                 : "+f"(c[0]), "+f"(c[1]), "+f"(c[2]), "+f"(c[3])
                 : "r"(a0), "r"(a1), "r"(a2), "r"(a3), "r"(b0), "r"(b1));
}
// 2 sign bits -> packed half2 of +-1 (bit=1 -> -1)
__device__ __forceinline__ uint32_t bexp(uint32_t t) {
    return 0x3C003C00u | ((t & 1u) << 15) | ((t & 2u) << 30);
}
// spread 16 bits to every 4th bit of a u64
__device__ __forceinline__ ull spr4(uint32_t x) {
    ull v = x & 0xFFFFull;
    v = (v | v << 24) & 0x000000FF000000FFull;
    v = (v | v << 12) & 0x000F000F000F000Full;
    v = (v | v << 6)  & 0x0303030303030303ull;
    v = (v | v << 3)  & 0x1111111111111111ull;
    return v;
}

// ---------------- pack kernels ----------------
// warp per codebook row: float4 loads, fp16 + spread-packed bits in one pass
__global__ void k_pack_cb(const float* __restrict__ cb) {
    int row  = blockIdx.x * 4 + (threadIdx.x >> 5);
    int lane = threadIdx.x & 31;
    const float* src = cb + (size_t)row * DD;
    __half* dsth = g_cb16 + (size_t)row * DD;
    ull* dstb = g_cbD + row * WD;
    #pragma unroll
    for (int i = 0; i < 8; i++) {
        int d = i * 128 + lane * 4;
        float4 v = *(const float4*)(src + d);
        __half2 h0 = __floats2half2_rn(v.x, v.y);
        __half2 h1 = __floats2half2_rn(v.z, v.w);
        uint2 st;
        st.x = *reinterpret_cast<unsigned*>(&h0);
        st.y = *reinterpret_cast<unsigned*>(&h1);
        *(uint2*)(dsth + d) = st;
        unsigned b0 = __ballot_sync(0xffffffffu, v.x < 0.f);
        unsigned b1 = __ballot_sync(0xffffffffu, v.y < 0.f);
        unsigned b2 = __ballot_sync(0xffffffffu, v.z < 0.f);
        unsigned b3 = __ballot_sync(0xffffffffu, v.w < 0.f);
        if (lane == 0) {
            dstb[i * 2]     = spr4(b0) | (spr4(b1) << 1) | (spr4(b2) << 2) | (spr4(b3) << 3);
            dstb[i * 2 + 1] = spr4(b0 >> 16) | (spr4(b1 >> 16) << 1) | (spr4(b2 >> 16) << 2) | (spr4(b3 >> 16) << 3);
        }
    }
}

__global__ void k_pack_est(const float* __restrict__ inp, const float* __restrict__ est0) {
    int row  = blockIdx.x * 4 + (threadIdx.x >> 5);
    int lane = threadIdx.x & 31;
    if (blockIdx.x == 0 && threadIdx.x < NITER) g_sync[threadIdx.x] = 0ull;
    const float* src;
    ull* dst;
    if (row < BB * FF) { src = est0 + (size_t)row * DD; dst = g_est[0] + row * WD; }
    else               { int b = row - BB * FF; src = inp + (size_t)b * DD; dst = g_in + b * WD; }
    ull lo = 0;
    #pragma unroll
    for (int i = 0; i < 32; i++) {
        unsigned bal = __ballot_sync(0xffffffffu, src[i * 32 + lane] < 0.f);
        if ((i & 1) == 0) lo = bal;
        else if (lane == 0) dst[i >> 1] = lo | ((ull)bal << 32);
    }
}

// ---------------- Gram matrix (fp16 HMMA): G[f][d][d'] = sum_m C[m,d]*C[m,d'] ----------------
// grid = 4 * 36 upper-triangle 128x128 tiles. K = 4096, chunks of 32, reg double-buffered.
__global__ void k_gram() {
    int f = blockIdx.x / 36, pair = blockIdx.x % 36;
    int i = 0, rem = pair;
    while (rem >= 8 - i) { rem -= 8 - i; i++; }
    int j = i + rem;
    int gi = i << 7, gj = j << 7;
    int t = threadIdx.x, lane = t & 31, w = t >> 5;
    int wm = w >> 1, wn = w & 1;            // warp tile 32m x 64n

    __shared__ __align__(16) __half sI[2][32 * 128];
    __shared__ __align__(16) __half sJ[2][32 * 128];

    const __half* Cf = g_cb16 + (size_t)f * MM * DD;

    float acc[2][8][4];
    #pragma unroll
    for (int a = 0; a < 2; a++)
        #pragma unroll
        for (int b2 = 0; b2 < 8; b2++)
            #pragma unroll
            for (int q = 0; q < 4; q++) acc[a][b2][q] = 0.f;

    uint4 rI[2], rJ[2];
    #pragma unroll
    for (int q = 0; q < 2; q++) {
        int id = t * 2 + q, r = id >> 4, cc = id & 15;
        rI[q] = *(const uint4*)(Cf + (size_t)r * DD + gi + cc * 8);
        rJ[q] = *(const uint4*)(Cf + (size_t)r * DD + gj + cc * 8);
    }
    #pragma unroll
    for (int q = 0; q < 2; q++) {
        int id = t * 2 + q, r = id >> 4, cc = id & 15, sub = cc >> 3, c8 = cc & 7;
        *(uint4*)(&sI[0][sub * 2048 + r * 64 + ((c8 ^ (r & 7)) << 3)]) = rI[q];
        *(uint4*)(&sJ[0][sub * 2048 + r * 64 + ((c8 ^ (r & 7)) << 3)]) = rJ[q];
    }

    for (int c = 0; c < 128; c++) {
        if (c + 1 < 128) {
            int k0 = (c + 1) * 32;
            #pragma unroll
            for (int q = 0; q < 2; q++) {
                int id = t * 2 + q, r = id >> 4, cc = id & 15;
                rI[q] = *(const uint4*)(Cf + (size_t)(k0 + r) * DD + gi + cc * 8);
                rJ[q] = *(const uint4*)(Cf + (size_t)(k0 + r) * DD + gj + cc * 8);
            }
        }
        __syncthreads();
        const __half* bI = sI[c & 1];
        const __half* bJ = sJ[c & 1];
        #pragma unroll
        for (int k16 = 0; k16 < 2; k16++) {
            uint32_t a_[2][4];
            #pragma unroll
            for (int mi = 0; mi < 2; mi++) {
                int col = wm * 32 + mi * 16;
                int sub = col >> 6, cl = col & 63;
                int rr = k16 * 16 + (lane & 15);
                int cc8 = (cl >> 3) + (lane >> 4);
                ldm_x4_t(a_[mi][0], a_[mi][1], a_[mi][2], a_[mi][3],
                         smem_u32(bI + sub * 2048 + rr * 64 + ((cc8 ^ (rr & 7)) << 3)));
            }
            #pragma unroll
            for (int ni = 0; ni < 4; ni++) {
                int col = wn * 64 + ni * 16;
                int sub = col >> 6, cl = col & 63;
                int rr = k16 * 16 + (lane & 15);
                int cc8 = (cl >> 3) + (lane >> 4);
                uint32_t b0, b1, b2, b3;
                ldm_x4_t(b0, b1, b2, b3,
                         smem_u32(bJ + sub * 2048 + rr * 64 + ((cc8 ^ (rr & 7)) << 3)));
                #pragma unroll
                for (int mi = 0; mi < 2; mi++) {
                    mma16816(acc[mi][ni * 2],     a_[mi][0], a_[mi][2], a_[mi][1], a_[mi][3], b0, b1);
                    mma16816(acc[mi][ni * 2 + 1], a_[mi][0], a_[mi][2], a_[mi][1], a_[mi][3], b2, b3);
                }
            }
        }
        if (c + 1 < 128) {
            int buf = (c + 1) & 1;
            #pragma unroll
            for (int q = 0; q < 2; q++) {
                int id = t * 2 + q, r = id >> 4, cc = id & 15, sub = cc >> 3, c8 = cc & 7;
                *(uint4*)(&sI[buf][sub * 2048 + r * 64 + ((c8 ^ (r & 7)) << 3)]) = rI[q];
                *(uint4*)(&sJ[buf][sub * 2048 + r * 64 + ((c8 ^ (r & 7)) << 3)]) = rJ[q];
            }
        }
    }

    __half* Gf = g_G + (size_t)f * DD * DD;
    #pragma unroll
    for (int mi = 0; mi < 2; mi++)
        #pragma unroll
        for (int nf = 0; nf < 8; nf++) {
            int row = gi + wm * 32 + mi * 16 + (lane >> 2);
            int col = gj + wn * 64 + nf * 8 + (lane & 3) * 2;
            float* cc = acc[mi][nf];
            *(__half2*)&Gf[(size_t)row * DD + col]       = __floats2half2_rn(cc[0], cc[1]);
            *(__half2*)&Gf[(size_t)(row + 8) * DD + col] = __floats2half2_rn(cc[2], cc[3]);
            if (i != j) {
                Gf[(size_t)col * DD + row]           = __float2half_rn(cc[0]);
                Gf[(size_t)(col + 1) * DD + row]     = __float2half_rn(cc[1]);
                Gf[(size_t)col * DD + row + 8]       = __float2half_rn(cc[2]);
                Gf[(size_t)(col + 1) * DD + row + 8] = __float2half_rn(cc[3]);
            }
        }
}

// ---------------- persistent kernel: 15 iterations + cleanup ----------------
// grid = 128 CTAs: f = bid>>5, nt = bid&31. 512 threads = 16 warps (wm=w&3 16m, kq=w>>2 256k).
// Round-5 proven mainloop; padded bits; distributed epilogue; packed-u64 barrier; early exit.
#define SM_BITS 131072
#define SM_CP   139776
#define SM_MM   173568
#define SM_TOT  173600

__global__ void __launch_bounds__(512) k_run(float* __restrict__ out, int out_size) {
    extern __shared__ __align__(16) char smem[];
    __half* sG    = (__half*)smem;                 // resident G slice (all iterations)
    ull*    sBits = (ull*)(smem + SM_BITS);        // [64][17]
    float*  sCp   = (float*)(smem + SM_CP);        // [4][64][33]
    int*    sMm   = (int*)(smem + SM_MM);          // [0]=mismatch cnt, [1]=global mm
    char*   aux   = smem;                          // cleanup scratch (sG dead then)

    int t = threadIdx.x, lane = t & 31, w = t >> 5;
    int wm = w & 3, kq = w >> 2;
    int f = blockIdx.x >> 5, nt = blockIdx.x & 31, n0 = nt << 5;

    // load resident G slice: 1024 rows x 32 cols into groups c8=0..3 of 128B swizzled rows
    {
        const __half* Gf = g_G + (size_t)f * DD * DD + n0;
        for (int idx = t; idx < 4096; idx += 512) {
            int r = idx >> 2, c8 = idx & 3;
            uint4 v = *(const uint4*)(Gf + (size_t)r * DD + c8 * 8);
            *(uint4*)(sG + r * 64 + ((c8 ^ (r & 7)) << 3)) = v;
        }
    }

    int lq = lane & 3, lh = lane >> 4, l15 = lane & 15;
    int r0 = wm * 16 + (lane >> 2), r1 = r0 + 8;
    int shb = lq * 2;
    int b8 = t >> 3, rg = t & 7;    // epilogue mapping

    for (int it = 0; it < NITER; it++) {
        int p = it & 1;
        const ull* E = g_est[p];
        if (t == 0) sMm[0] = 0;

        // new_est bits: in ^ (xor of all est) ^ est_f  (padded rows)
        for (int idx = t; idx < BB * WD; idx += 512) {
            int b = idx >> 4, wd = idx & 15;
            ull x = g_in[idx];
            x ^= E[(b * FF + 0) * WD + wd] ^ E[(b * FF + 1) * WD + wd]
               ^ E[(b * FF + 2) * WD + wd] ^ E[(b * FF + 3) * WD + wd];
            sBits[b * WDP + wd] = x ^ E[(b * FF + f) * WD + wd];
        }
        __syncthreads();   // bits + (it=0) G-load visible

        float acc[4][4];
        #pragma unroll
        for (int a = 0; a < 4; a++)
            #pragma unroll
            for (int q = 0; q < 4; q++) acc[a][q] = 0.f;

        // round-5 mainloop: A from bits (regs), B via ldmatrix from resident sG
        #pragma unroll
        for (int c4 = 0; c4 < 4; c4++) {
            int C = kq * 4 + c4;
            ull w0 = sBits[r0 * WDP + C];
            ull w1 = sBits[r1 * WDP + C];
            #pragma unroll
            for (int k16 = 0; k16 < 4; k16++) {
                int sh = k16 * 16 + shb;
                uint32_t t0 = (uint32_t)(w0 >> sh), t1 = (uint32_t)(w1 >> sh);
                uint32_t a0 = bexp(t0), a1 = bexp(t1);
                uint32_t a2 = bexp(t0 >> 8), a3 = bexp(t1 >> 8);
                int br = C * 64 + k16 * 16 + l15;
                uint32_t b0, b1, b2, b3;
                int bc8 = lh;
                ldm_x4_t(b0, b1, b2, b3, smem_u32(sG + br * 64 + ((bc8 ^ (br & 7)) << 3)));
                mma16816(acc[0], a0, a1, a2, a3, b0, b1);
                mma16816(acc[1], a0, a1, a2, a3, b2, b3);
                bc8 = 2 + lh;
                ldm_x4_t(b0, b1, b2, b3, smem_u32(sG + br * 64 + ((bc8 ^ (br & 7)) << 3)));
                mma16816(acc[2], a0, a1, a2, a3, b0, b1);
                mma16816(acc[3], a0, a1, a2, a3, b2, b3);
            }
        }

        // stage K-partials: sCp[kq][64][33]
        {
            float* P = sCp + kq * 2112;
            #pragma unroll
            for (int j = 0; j < 4; j++) {
                P[r0 * 33 + j * 8 + shb]     = acc[j][0];
                P[r0 * 33 + j * 8 + shb + 1] = acc[j][1];
                P[r1 * 33 + j * 8 + shb]     = acc[j][2];
                P[r1 * 33 + j * 8 + shb + 1] = acc[j][3];
            }
        }
        __syncthreads();

        // distributed reduce + pack: thread = (batch b8, col-group rg of 4)
        {
            uint32_t word = 0;
            #pragma unroll
            for (int i2 = 0; i2 < 4; i2++) {
                int col = rg * 4 + i2;
                float s = sCp[b8 * 33 + col] + sCp[2112 + b8 * 33 + col]
                        + sCp[4224 + b8 * 33 + col] + sCp[6336 + b8 * 33 + col];
                word |= (uint32_t)(s < 0.f) << col;    // sign(0)=+1 -> strict <0
            }
            word |= __shfl_down_sync(0xffffffffu, word, 4, 8);
            word |= __shfl_down_sync(0xffffffffu, word, 2, 8);
            word |= __shfl_down_sync(0xffffffffu, word, 1, 8);
            bool chg = false;
            if (rg == 0) {
                int ei = (b8 * FF + f) * 32 + nt;
                uint32_t old = ((const uint32_t*)g_est[p])[ei];
                ((uint32_t*)g_est[p ^ 1])[ei] = word;
                chg = (word != old);
            }
            unsigned msk = __ballot_sync(0xffffffffu, chg);
            if (lane == 0 && msk) atomicAdd(&sMm[0], __popc(msk));
        }
        __syncthreads();

        // packed barrier: one release-atomic per CTA (arrive + mismatch), thread0 polls
        if (t == 0) {
            asm volatile("membar.gl;" ::: "memory");
            ull val = 1ull | ((ull)(unsigned)sMm[0] << 32);
            asm volatile("red.release.gpu.global.add.u64 [%0], %1;"
                         :: "l"(g_sync + it), "l"(val) : "memory");
            ull v;
            do {
                asm volatile("ld.acquire.gpu.global.b64 %0, [%1];"
                             : "=l"(v) : "l"(g_sync + it) : "memory");
            } while ((unsigned)v < GRID_RUN);
            sMm[1] = (int)(v >> 32);
        }
        __syncthreads();
        if (sMm[1] == 0) break;   // fixed point: all later iterations identical
    }
    __syncthreads();

    // ---------------- cleanup: argmax|sim| per (b, f), est floats, iters/conv ----------------
    {
        int f2 = blockIdx.x >> 5, bg = blockIdx.x & 31;   // 2 batches per CTA
        ull* sE = (ull*)aux;                              // 2 x 16 ull
        int* rA = (int*)(aux + 256);
        int* rI = (int*)(aux + 256 + 2048);
        const ull* Ef = g_est[NITER & 1];

        if (t < 32) {
            int j = t >> 4, wd = t & 15;
            sE[j * WD + wd] = Ef[(size_t)((bg * 2 + j) * FF + f2) * WD + wd];
        }
        __syncthreads();

        const ull* cb = g_cbD + (size_t)f2 * MM * WD;
        int bestA[2] = {-1, -1}, bestI[2] = {0, 0};
        for (int m = t; m < MM; m += 512) {
            ull rb[WD];
            const ull* rp = cb + (size_t)m * WD;
            #pragma unroll
            for (int q = 0; q < WD; q++) rb[q] = rp[q];
            #pragma unroll
            for (int j = 0; j < 2; j++) {
                int h = 0;
                #pragma unroll
                for (int q = 0; q < WD; q++) h += __popcll(rb[q] ^ sE[j * WD + q]);
                int s = DD - 2 * h;
                int a = s < 0 ? -s : s;
                if (a > bestA[j]) { bestA[j] = a; bestI[j] = m; }
            }
        }

        #pragma unroll
        for (int j = 0; j < 2; j++) {
            __syncthreads();
            rA[t] = bestA[j]; rI[t] = bestI[j];
            __syncthreads();
            for (int off = 256; off; off >>= 1) {
                if (t < off) {
                    int a2 = rA[t + off], i2 = rI[t + off];
                    if (a2 > rA[t] || (a2 == rA[t] && i2 < rI[t])) { rA[t] = a2; rI[t] = i2; }
                }
                __syncthreads();
            }
            int idx = (bg * 2 + j) * FF + f2;
            if (t == 0 && idx < out_size) out[idx] = (float)rI[0];
            if (out_size >= 256 + BB * FF * DD) {
                float* oe = out + 256 + (size_t)idx * DD;
                for (int d = t; d < DD; d += 512) {
                    int bit = (int)((sE[j * WD + (d >> 6)] >> (d & 63)) & 1ULL);
                    oe[d] = bit ? -1.f : 1.f;
                }
            }
        }

        if (blockIdx.x == 0 && t == 0 && out_size >= 256 + BB * FF * DD + 2) {
            int iters = NITER, conv = 0;
            for (int tt = 0; tt < NITER; tt++)
                if ((int)(g_sync[tt] >> 32) == 0) { iters = tt + 1; conv = 1; break; }
            out[256 + BB * FF * DD]     = (float)iters;
            out[256 + BB * FF * DD + 1] = (float)conv;
        }
    }
}

// ---------------- launch ----------------
extern "C" void kernel_launch(void* const* d_in, const int* in_sizes, int n_in,
                              void* d_out, int out_size) {
    const float* input = nullptr;
    const float* est0  = nullptr;
    const float* cb    = nullptr;
    for (int i = 0; i < n_in; i++) {
        if (in_sizes[i] == BB * DD)            input = (const float*)d_in[i];
        else if (in_sizes[i] == BB * FF * DD)  est0  = (const float*)d_in[i];
        else if (in_sizes[i] == FF * MM * DD)  cb    = (const float*)d_in[i];
    }
    cudaFuncSetAttribute(k_run, cudaFuncAttributeMaxDynamicSharedMemorySize, SM_TOT);
    k_pack_est<<<80, 128>>>(input, est0);
    k_pack_cb<<<FF * MM / 4, 128>>>(cb);
    k_gram<<<FF * 36, 256>>>();
    k_run<<<GRID_RUN, 512, SM_TOT>>>((float*)d_out, out_size);
}